// round 4
// baseline (speedup 1.0000x reference)
#include <cuda_runtime.h>
#include <math.h>

#define BB   2
#define NN   20000
#define EE   200000
#define INF_ 256
#define OUTF 32
#define NH   4
#define HF   128          // NH*OUTF
#define ROWS 40000        // BB*NN
#define NEG_SLOPE 0.2f

// ---------------- scratch (device globals; no allocation allowed) ----------
__device__ float g_h[(size_t)ROWS * HF];       // 20.48 MB: h[b*NN+n][h*32+f]
__device__ float g_s_src[ROWS * NH];
__device__ float g_s_dst[ROWS * NH];
__device__ float g_aw[ROWS * NH];
__device__ int   g_last_edge[NN];
__device__ int   g_src[EE];                    // canonical int32 edge arrays
__device__ int   g_dst[EE];
__device__ int   g_idx_is32;                   // 1 if edges stored as int32

static __device__ __forceinline__ int clampN(int v) {
    v = v < 0 ? 0 : v;
    return v >= NN ? NN - 1 : v;
}

// ---------------- 0a) probe edge dtype -------------------------------------
// If the edge buffer really holds int64, every 8-byte value is in [0, NN).
// If it holds int32 data, 8-byte reads are packed pairs whose high word is
// a node id (nonzero with prob 1-1/20000 per entry) -> flagged bad.
// Sample 128 entries from the front and 128 from the middle.
__global__ void probe_kernel(const void* __restrict__ ei_raw) {
    __shared__ int bad;
    if (threadIdx.x == 0) bad = 0;
    __syncthreads();
    const long long* e64 = (const long long*)ei_raw;
    int idx = (threadIdx.x < 128) ? threadIdx.x : (100000 + threadIdx.x - 128);
    long long v = e64[idx];
    if (v < 0 || v >= NN) atomicExch(&bad, 1);
    __syncthreads();
    if (threadIdx.x == 0) g_idx_is32 = bad;
}

// ---------------- 0b) canonicalize edges to int32 --------------------------
__global__ void convert_kernel(const void* __restrict__ ei_raw) {
    int e = blockIdx.x * blockDim.x + threadIdx.x;
    if (e >= EE) return;
    int s, d;
    if (g_idx_is32) {
        const int* p = (const int*)ei_raw;
        s = p[e];
        d = p[EE + e];
    } else {
        const long long* p = (const long long*)ei_raw;
        s = (int)p[e];
        d = (int)p[EE + e];
    }
    g_src[e] = clampN(s);
    g_dst[e] = clampN(d);
}

// ---------------- 1) h = x @ W^T  (fp32 scalar FFMA, validated path) -------
// M=40000, N=128, K=256. BM=64, BN=128, BK=32, TM=8, TN=8, 128 threads.
__global__ void __launch_bounds__(128) gemm_kernel(const float* __restrict__ x,
                                                   const float* __restrict__ W) {
    __shared__ float xs[64][36];    // [m][k], pad to kill STS conflicts
    __shared__ float ws[32][128];   // [k][n] transposed

    const int tid = threadIdx.x;
    const int tx  = tid & 15;       // cols tx*8 .. tx*8+7
    const int ty  = tid >> 4;       // rows ty*8 .. ty*8+7
    const int m0  = blockIdx.x * 64;

    float acc[8][8];
    #pragma unroll
    for (int i = 0; i < 8; i++)
        #pragma unroll
        for (int j = 0; j < 8; j++) acc[i][j] = 0.f;

    for (int k0 = 0; k0 < INF_; k0 += 32) {
        #pragma unroll
        for (int i = 0; i < 4; i++) {
            int idx = tid + i * 128;        // 0..511 float4 slots
            int r   = idx >> 3;
            int kq  = idx & 7;
            float4 v = *reinterpret_cast<const float4*>(
                x + (size_t)(m0 + r) * INF_ + k0 + kq * 4);
            *reinterpret_cast<float4*>(&xs[r][kq * 4]) = v;
        }
        {
            int n = tid;                    // 0..127
            #pragma unroll
            for (int kq = 0; kq < 8; kq++) {
                float4 v = *reinterpret_cast<const float4*>(
                    W + (size_t)n * INF_ + k0 + kq * 4);
                ws[kq * 4 + 0][n] = v.x;
                ws[kq * 4 + 1][n] = v.y;
                ws[kq * 4 + 2][n] = v.z;
                ws[kq * 4 + 3][n] = v.w;
            }
        }
        __syncthreads();

        #pragma unroll
        for (int k = 0; k < 32; k++) {
            float wv[8];
            float4 wa = *reinterpret_cast<const float4*>(&ws[k][tx * 8]);
            float4 wb = *reinterpret_cast<const float4*>(&ws[k][tx * 8 + 4]);
            wv[0] = wa.x; wv[1] = wa.y; wv[2] = wa.z; wv[3] = wa.w;
            wv[4] = wb.x; wv[5] = wb.y; wv[6] = wb.z; wv[7] = wb.w;
            #pragma unroll
            for (int i = 0; i < 8; i++) {
                float rm = xs[ty * 8 + i][k];
                #pragma unroll
                for (int j = 0; j < 8; j++) acc[i][j] = fmaf(rm, wv[j], acc[i][j]);
            }
        }
        __syncthreads();
    }

    #pragma unroll
    for (int i = 0; i < 8; i++) {
        float* orow = g_h + (size_t)(m0 + ty * 8 + i) * HF + tx * 8;
        *reinterpret_cast<float4*>(orow) =
            make_float4(acc[i][0], acc[i][1], acc[i][2], acc[i][3]);
        *reinterpret_cast<float4*>(orow + 4) =
            make_float4(acc[i][4], acc[i][5], acc[i][6], acc[i][7]);
    }
}

// ---------------- 2) per-node attention scores -----------------------------
__global__ void score_kernel(const float* __restrict__ a) {
    int row  = blockIdx.x * 8 + (threadIdx.x >> 5);
    if (row >= ROWS) return;
    int lane = threadIdx.x & 31;

    float asv = a[lane];
    float adv = a[32 + lane];
    const float* hr = g_h + (size_t)row * HF;

    float ps[4], pd[4];
    #pragma unroll
    for (int hh = 0; hh < 4; hh++) {
        float v = hr[hh * 32 + lane];
        ps[hh] = v * asv;
        pd[hh] = v * adv;
    }
    #pragma unroll
    for (int off = 16; off; off >>= 1) {
        #pragma unroll
        for (int hh = 0; hh < 4; hh++) {
            ps[hh] += __shfl_xor_sync(0xFFFFFFFFu, ps[hh], off);
            pd[hh] += __shfl_xor_sync(0xFFFFFFFFu, pd[hh], off);
        }
    }
    if (lane == 0) {
        #pragma unroll
        for (int hh = 0; hh < 4; hh++) {
            g_s_src[row * NH + hh] = ps[hh];
            g_s_dst[row * NH + hh] = pd[hh];
        }
    }
}

// ---------------- 3) init: zero out, last_edge = -1 ------------------------
__global__ void init_kernel(float* __restrict__ out) {
    int i = blockIdx.x * blockDim.x + threadIdx.x;
    if (i < BB * NN * OUTF) out[i] = 0.f;
    if (i < NN)             g_last_edge[i] = -1;
}

// ---------------- 4) last edge per source node -----------------------------
__global__ void lastedge_kernel() {
    int e = blockIdx.x * blockDim.x + threadIdx.x;
    if (e < EE) atomicMax(&g_last_edge[g_src[e]], e);
}

// ---------------- 5) attention weights (2-way softmax over batch) ----------
__global__ void aw_kernel() {
    int n = blockIdx.x * blockDim.x + threadIdx.x;
    if (n >= NN) return;
    int le = g_last_edge[n];
    if (le < 0) {
        #pragma unroll
        for (int hh = 0; hh < 4; hh++) {
            g_aw[n * NH + hh] = 0.f;
            g_aw[(NN + n) * NH + hh] = 0.f;
        }
        return;
    }
    int d = g_dst[le];
    #pragma unroll
    for (int hh = 0; hh < 4; hh++) {
        float z0 = g_s_src[n * NH + hh]        + g_s_dst[d * NH + hh];
        float z1 = g_s_src[(NN + n) * NH + hh] + g_s_dst[(NN + d) * NH + hh];
        z0 = z0 > 0.f ? z0 : NEG_SLOPE * z0;
        z1 = z1 > 0.f ? z1 : NEG_SLOPE * z1;
        float m  = fmaxf(z0, z1);
        float e0 = __expf(z0 - m);
        float e1 = __expf(z1 - m);
        float inv = 1.f / (e0 + e1);
        g_aw[n * NH + hh]        = e0 * inv;
        g_aw[(NN + n) * NH + hh] = e1 * inv;
    }
}

// ---------------- 6) edge aggregation with fused aw + head-mean ------------
// thread t: e = t>>4, sub = t&15 -> (b = sub>>3, f4 = sub&7 covering 4 f's)
// out[b,src,f] += 0.25 * sum_h aw[b,src,h] * h[b,dst,h*32+f]
__global__ void agg_kernel(float* __restrict__ out) {
    unsigned t = blockIdx.x * 256u + threadIdx.x;
    unsigned e = t >> 4;
    if (e >= EE) return;
    unsigned sub = t & 15u;
    unsigned b   = sub >> 3;
    unsigned f4  = sub & 7u;

    int s = g_src[e];
    int d = g_dst[e];

    const float4* hr = reinterpret_cast<const float4*>(
        g_h + (size_t)(b * NN + d) * HF) + f4;
    float4 aw = *reinterpret_cast<const float4*>(g_aw + (size_t)(b * NN + s) * NH);

    float4 h0 = hr[0], h1 = hr[8], h2 = hr[16], h3 = hr[24];
    float rx = 0.25f * (aw.x * h0.x + aw.y * h1.x + aw.z * h2.x + aw.w * h3.x);
    float ry = 0.25f * (aw.x * h0.y + aw.y * h1.y + aw.z * h2.y + aw.w * h3.y);
    float rz = 0.25f * (aw.x * h0.z + aw.y * h1.z + aw.z * h2.z + aw.w * h3.z);
    float rw = 0.25f * (aw.x * h0.w + aw.y * h1.w + aw.z * h2.w + aw.w * h3.w);

    float* op = out + (size_t)(b * NN + s) * OUTF + f4 * 4;
    asm volatile("red.global.add.v4.f32 [%0], {%1,%2,%3,%4};"
                 :: "l"(op), "f"(rx), "f"(ry), "f"(rz), "f"(rw) : "memory");
}

// ---------------- launch ---------------------------------------------------
extern "C" void kernel_launch(void* const* d_in, const int* in_sizes, int n_in,
                              void* d_out, int out_size) {
    // Identify inputs by unique element counts (robust to metadata ordering
    // AND to int64 edges being reported as either 400000 or 800000 elems):
    //   x: 10,240,000   edge_indices: 400,000 (or 800,000)   W: 32,768   a: 64
    const float* x  = nullptr;
    const void*  ei = nullptr;
    const float* W  = nullptr;
    const float* a  = nullptr;
    for (int i = 0; i < n_in; i++) {
        switch (in_sizes[i]) {
            case 10240000: x  = (const float*)d_in[i]; break;
            case 400000:   ei = d_in[i];               break;
            case 800000:   ei = d_in[i];               break;
            case 32768:    W  = (const float*)d_in[i]; break;
            case 64:       a  = (const float*)d_in[i]; break;
            default: break;
        }
    }
    float* out = (float*)d_out;

    probe_kernel<<<1, 256>>>(ei);
    convert_kernel<<<(EE + 255) / 256, 256>>>(ei);
    init_kernel<<<(BB * NN * OUTF + 255) / 256, 256>>>(out);
    gemm_kernel<<<ROWS / 64, 128>>>(x, W);
    score_kernel<<<ROWS / 8, 256>>>(a);
    lastedge_kernel<<<(EE + 255) / 256, 256>>>();
    aw_kernel<<<(NN + 255) / 256, 256>>>();
    agg_kernel<<<(EE * 16) / 256, 256>>>(out);
}

// round 10
// speedup vs baseline: 1.0679x; 1.0679x over previous
#include <cuda_runtime.h>
#include <math.h>

#define BB   2
#define NN   20000
#define EE   200000
#define INF_ 256
#define OUTF 32
#define NH   4
#define HF   128          // NH*OUTF
#define ROWS 40000        // BB*NN
#define NEG_SLOPE 0.2f

// ---------------- scratch (device globals; no allocation allowed) ----------
__device__ float g_h[(size_t)ROWS * HF];       // 20.48 MB: h[b*NN+n][h*32+f]
__device__ float g_s_src[ROWS * NH];
__device__ float g_s_dst[ROWS * NH];
__device__ float g_aw[ROWS * NH];
__device__ int   g_last_edge[NN];
__device__ int   g_src[EE];                    // canonical int32 edge arrays
__device__ int   g_dst[EE];
__device__ int   g_idx_is32;                   // 1 if edges stored as int32

static __device__ __forceinline__ int clampN(int v) {
    v = v < 0 ? 0 : v;
    return v >= NN ? NN - 1 : v;
}

// ---------------- packed f32x2 helpers (Blackwell FFMA2 path) --------------
static __device__ __forceinline__ unsigned long long pk2(float lo, float hi) {
    unsigned long long r;
    asm("mov.b64 %0, {%1, %2};" : "=l"(r) : "f"(lo), "f"(hi));
    return r;
}
static __device__ __forceinline__ unsigned long long ffma2(unsigned long long a,
                                                           unsigned long long b,
                                                           unsigned long long c) {
    unsigned long long d;
    asm("fma.rn.f32x2 %0, %1, %2, %3;" : "=l"(d) : "l"(a), "l"(b), "l"(c));
    return d;
}
static __device__ __forceinline__ float2 upk2(unsigned long long v) {
    float lo, hi;
    asm("mov.b64 {%0, %1}, %2;" : "=f"(lo), "=f"(hi) : "l"(v));
    return make_float2(lo, hi);
}

// ---------------- 0a) probe edge dtype -------------------------------------
__global__ void probe_kernel(const void* __restrict__ ei_raw) {
    __shared__ int bad;
    if (threadIdx.x == 0) bad = 0;
    __syncthreads();
    const long long* e64 = (const long long*)ei_raw;
    int idx = (threadIdx.x < 128) ? threadIdx.x : (100000 + threadIdx.x - 128);
    long long v = e64[idx];
    if (v < 0 || v >= NN) atomicExch(&bad, 1);
    __syncthreads();
    if (threadIdx.x == 0) g_idx_is32 = bad;
}

// ---------------- 0b) init: zero out, last_edge = -1 (BEFORE convert) ------
__global__ void init_kernel(float* __restrict__ out) {
    int i = blockIdx.x * blockDim.x + threadIdx.x;
    if (i < BB * NN * OUTF) out[i] = 0.f;
    if (i < NN)             g_last_edge[i] = -1;
}

// ---------------- 0c) canonicalize edges + fused last-edge atomicMax -------
// Requires g_last_edge pre-initialized to -1 (init_kernel runs first).
__global__ void convert_kernel(const void* __restrict__ ei_raw) {
    int e = blockIdx.x * blockDim.x + threadIdx.x;
    if (e >= EE) return;
    int s, d;
    if (g_idx_is32) {
        const int* p = (const int*)ei_raw;
        s = p[e];
        d = p[EE + e];
    } else {
        const long long* p = (const long long*)ei_raw;
        s = (int)p[e];
        d = (int)p[EE + e];
    }
    s = clampN(s);
    d = clampN(d);
    g_src[e] = s;
    g_dst[e] = d;
    atomicMax(&g_last_edge[s], e);      // fused: was a separate kernel
}

// ---------------- 1) h = x @ W^T  (fp32 via packed FFMA2) ------------------
// M=40000, N=128, K=256. BM=64, BN=128, BK=32, TM=8, TN=8, 128 threads.
// Single pending delta vs the validated scalar-FFMA version (R4, 94.3us):
// the fma.rn.f32x2 inner product (64 FFMA -> 32 FFMA2 per k-step).
__global__ void __launch_bounds__(128) gemm_kernel(const float* __restrict__ x,
                                                   const float* __restrict__ W) {
    __shared__ float xs[64][36];    // [m][k], pad to kill STS conflicts
    __shared__ float ws[32][128];   // [k][n] transposed

    const int tid = threadIdx.x;
    const int tx  = tid & 15;       // cols tx*8 .. tx*8+7
    const int ty  = tid >> 4;       // rows ty*8 .. ty*8+7
    const int m0  = blockIdx.x * 64;

    unsigned long long acc[8][4];   // [row][col-pair], lo=col 2j, hi=col 2j+1
    #pragma unroll
    for (int i = 0; i < 8; i++)
        #pragma unroll
        for (int j = 0; j < 4; j++) acc[i][j] = pk2(0.f, 0.f);

    for (int k0 = 0; k0 < INF_; k0 += 32) {
        #pragma unroll
        for (int i = 0; i < 4; i++) {
            int idx = tid + i * 128;        // 0..511 float4 slots
            int r   = idx >> 3;
            int kq  = idx & 7;
            float4 v = *reinterpret_cast<const float4*>(
                x + (size_t)(m0 + r) * INF_ + k0 + kq * 4);
            *reinterpret_cast<float4*>(&xs[r][kq * 4]) = v;
        }
        {
            int n = tid;                    // 0..127
            #pragma unroll
            for (int kq = 0; kq < 8; kq++) {
                float4 v = *reinterpret_cast<const float4*>(
                    W + (size_t)n * INF_ + k0 + kq * 4);
                ws[kq * 4 + 0][n] = v.x;
                ws[kq * 4 + 1][n] = v.y;
                ws[kq * 4 + 2][n] = v.z;
                ws[kq * 4 + 3][n] = v.w;
            }
        }
        __syncthreads();

        #pragma unroll
        for (int k = 0; k < 32; k++) {
            float4 wa = *reinterpret_cast<const float4*>(&ws[k][tx * 8]);
            float4 wb = *reinterpret_cast<const float4*>(&ws[k][tx * 8 + 4]);
            unsigned long long bn0 = pk2(wa.x, wa.y);
            unsigned long long bn1 = pk2(wa.z, wa.w);
            unsigned long long bn2 = pk2(wb.x, wb.y);
            unsigned long long bn3 = pk2(wb.z, wb.w);
            #pragma unroll
            for (int i = 0; i < 8; i++) {
                float rm = xs[ty * 8 + i][k];        // broadcast LDS
                unsigned long long am = pk2(rm, rm);
                acc[i][0] = ffma2(am, bn0, acc[i][0]);
                acc[i][1] = ffma2(am, bn1, acc[i][1]);
                acc[i][2] = ffma2(am, bn2, acc[i][2]);
                acc[i][3] = ffma2(am, bn3, acc[i][3]);
            }
        }
        __syncthreads();
    }

    #pragma unroll
    for (int i = 0; i < 8; i++) {
        float2 c0 = upk2(acc[i][0]);
        float2 c1 = upk2(acc[i][1]);
        float2 c2 = upk2(acc[i][2]);
        float2 c3 = upk2(acc[i][3]);
        float* orow = g_h + (size_t)(m0 + ty * 8 + i) * HF + tx * 8;
        *reinterpret_cast<float4*>(orow)     = make_float4(c0.x, c0.y, c1.x, c1.y);
        *reinterpret_cast<float4*>(orow + 4) = make_float4(c2.x, c2.y, c3.x, c3.y);
    }
}

// ---------------- 2) per-node attention scores -----------------------------
__global__ void score_kernel(const float* __restrict__ a) {
    int row  = blockIdx.x * 8 + (threadIdx.x >> 5);
    if (row >= ROWS) return;
    int lane = threadIdx.x & 31;

    float asv = a[lane];
    float adv = a[32 + lane];
    const float* hr = g_h + (size_t)row * HF;

    float ps[4], pd[4];
    #pragma unroll
    for (int hh = 0; hh < 4; hh++) {
        float v = hr[hh * 32 + lane];
        ps[hh] = v * asv;
        pd[hh] = v * adv;
    }
    #pragma unroll
    for (int off = 16; off; off >>= 1) {
        #pragma unroll
        for (int hh = 0; hh < 4; hh++) {
            ps[hh] += __shfl_xor_sync(0xFFFFFFFFu, ps[hh], off);
            pd[hh] += __shfl_xor_sync(0xFFFFFFFFu, pd[hh], off);
        }
    }
    if (lane == 0) {
        #pragma unroll
        for (int hh = 0; hh < 4; hh++) {
            g_s_src[row * NH + hh] = ps[hh];
            g_s_dst[row * NH + hh] = pd[hh];
        }
    }
}

// ---------------- 5) attention weights (2-way softmax over batch) ----------
__global__ void aw_kernel() {
    int n = blockIdx.x * blockDim.x + threadIdx.x;
    if (n >= NN) return;
    int le = g_last_edge[n];
    if (le < 0) {
        #pragma unroll
        for (int hh = 0; hh < 4; hh++) {
            g_aw[n * NH + hh] = 0.f;
            g_aw[(NN + n) * NH + hh] = 0.f;
        }
        return;
    }
    int d = g_dst[le];
    #pragma unroll
    for (int hh = 0; hh < 4; hh++) {
        float z0 = g_s_src[n * NH + hh]        + g_s_dst[d * NH + hh];
        float z1 = g_s_src[(NN + n) * NH + hh] + g_s_dst[(NN + d) * NH + hh];
        z0 = z0 > 0.f ? z0 : NEG_SLOPE * z0;
        z1 = z1 > 0.f ? z1 : NEG_SLOPE * z1;
        float m  = fmaxf(z0, z1);
        float e0 = __expf(z0 - m);
        float e1 = __expf(z1 - m);
        float inv = 1.f / (e0 + e1);
        g_aw[n * NH + hh]        = e0 * inv;
        g_aw[(NN + n) * NH + hh] = e1 * inv;
    }
}

// ---------------- 6) edge aggregation with fused aw + head-mean ------------
__global__ void agg_kernel(float* __restrict__ out) {
    unsigned t = blockIdx.x * 256u + threadIdx.x;
    unsigned e = t >> 4;
    if (e >= EE) return;
    unsigned sub = t & 15u;
    unsigned b   = sub >> 3;
    unsigned f4  = sub & 7u;

    int s = g_src[e];
    int d = g_dst[e];

    const float4* hr = reinterpret_cast<const float4*>(
        g_h + (size_t)(b * NN + d) * HF) + f4;
    float4 aw = *reinterpret_cast<const float4*>(g_aw + (size_t)(b * NN + s) * NH);

    float4 h0 = hr[0], h1 = hr[8], h2 = hr[16], h3 = hr[24];
    float rx = 0.25f * (aw.x * h0.x + aw.y * h1.x + aw.z * h2.x + aw.w * h3.x);
    float ry = 0.25f * (aw.x * h0.y + aw.y * h1.y + aw.z * h2.y + aw.w * h3.y);
    float rz = 0.25f * (aw.x * h0.z + aw.y * h1.z + aw.z * h2.z + aw.w * h3.z);
    float rw = 0.25f * (aw.x * h0.w + aw.y * h1.w + aw.z * h2.w + aw.w * h3.w);

    float* op = out + (size_t)(b * NN + s) * OUTF + f4 * 4;
    asm volatile("red.global.add.v4.f32 [%0], {%1,%2,%3,%4};"
                 :: "l"(op), "f"(rx), "f"(ry), "f"(rz), "f"(rw) : "memory");
}

// ---------------- launch ---------------------------------------------------
extern "C" void kernel_launch(void* const* d_in, const int* in_sizes, int n_in,
                              void* d_out, int out_size) {
    const float* x  = nullptr;
    const void*  ei = nullptr;
    const float* W  = nullptr;
    const float* a  = nullptr;
    for (int i = 0; i < n_in; i++) {
        switch (in_sizes[i]) {
            case 10240000: x  = (const float*)d_in[i]; break;
            case 400000:   ei = d_in[i];               break;
            case 800000:   ei = d_in[i];               break;
            case 32768:    W  = (const float*)d_in[i]; break;
            case 64:       a  = (const float*)d_in[i]; break;
            default: break;
        }
    }
    float* out = (float*)d_out;

    probe_kernel<<<1, 256>>>(ei);
    init_kernel<<<(BB * NN * OUTF + 255) / 256, 256>>>(out);   // before convert!
    convert_kernel<<<(EE + 255) / 256, 256>>>(ei);             // + fused lastedge
    gemm_kernel<<<ROWS / 64, 128>>>(x, W);
    score_kernel<<<ROWS / 8, 256>>>(a);
    aw_kernel<<<(NN + 255) / 256, 256>>>();
    agg_kernel<<<(EE * 16) / 256, 256>>>(out);
}